// round 8
// baseline (speedup 1.0000x reference)
#include <cuda_runtime.h>
#include <cuda_bf16.h>
#include <cstdint>

// Problem constants
#define BB 4
#define LL 2048
#define EE 1024
#define HH 16
#define DD 64
#define MM (BB * LL)          // 8192
#define NQKV 4096             // 2048 (q+gate) + 1024 (k) + 1024 (v)

// Scratch (device globals; no allocation allowed)
__device__ float g_qkv[(size_t)MM * NQKV];          // fused projection output
__device__ float g_q[(size_t)BB * HH * LL * DD];    // [B*H, L, D] after norm+rope
__device__ float g_k[(size_t)BB * HH * LL * DD];
__device__ float g_v[(size_t)BB * HH * LL * DD];
__device__ float g_gate[(size_t)MM * HH * DD];      // [B,L,H*D] raw gate
__device__ float g_x[(size_t)MM * HH * DD];         // gated attention output [B,L,H*D]

// ---------------------------------------------------------------------------
// 128x128x16 fp32 GEMM body, 2-stage smem double buffer.
// C[rowBase:+128, colC:+128] = A[rowBase:+128, 0:K] @ W[0:K, colW:+128]
// 256 threads, 8x8 per-thread tile. One __syncthreads per k-step.
// ---------------------------------------------------------------------------
__device__ __forceinline__ void sgemm_body(
    const float* __restrict__ A, int lda,
    const float* __restrict__ W, int ldw,
    float* __restrict__ C, int ldc,
    int K, int rowBase, int colW, int colC)
{
    __shared__ float As[2][16][132];   // transposed: As[buf][k][m]
    __shared__ float Bs[2][16][132];   // Bs[buf][k][n]

    const int tid = threadIdx.x;
    const int tx = tid & 15;        // 0..15 -> n
    const int ty = tid >> 4;        // 0..15 -> m

    float acc[8][8];
#pragma unroll
    for (int i = 0; i < 8; ++i)
#pragma unroll
        for (int j = 0; j < 8; ++j) acc[i][j] = 0.f;

    const int aRow = tid >> 2;          // 0..63
    const int aCol = (tid & 3) * 4;     // 0,4,8,12
    const int bRow = tid >> 5;          // 0..7
    const int bCol = (tid & 31) * 4;    // 0..124

    const float* Abase = A + (size_t)rowBase * lda;

    // Preload tile 0 into buffer 0
#pragma unroll
    for (int i = 0; i < 2; ++i) {
        int r = aRow + i * 64;
        float4 av = *(const float4*)(Abase + (size_t)r * lda + aCol);
        As[0][aCol + 0][r] = av.x;
        As[0][aCol + 1][r] = av.y;
        As[0][aCol + 2][r] = av.z;
        As[0][aCol + 3][r] = av.w;
    }
#pragma unroll
    for (int i = 0; i < 2; ++i) {
        int r = bRow + i * 8;
        float4 wv4 = *(const float4*)(W + (size_t)r * ldw + colW + bCol);
        *(float4*)&Bs[0][r][bCol] = wv4;
    }
    __syncthreads();

    int buf = 0;
    for (int k0 = 16; k0 < K; k0 += 16) {
        // Prefetch next tile into registers (hides DRAM/L2 latency behind compute)
        float4 aReg[2], bReg[2];
#pragma unroll
        for (int i = 0; i < 2; ++i) {
            int r = aRow + i * 64;
            aReg[i] = *(const float4*)(Abase + (size_t)r * lda + k0 + aCol);
        }
#pragma unroll
        for (int i = 0; i < 2; ++i) {
            int r = bRow + i * 8;
            bReg[i] = *(const float4*)(W + (size_t)(k0 + r) * ldw + colW + bCol);
        }

        // Compute on current buffer
#pragma unroll
        for (int k = 0; k < 16; ++k) {
            float a[8], b[8];
            *(float4*)(a)     = *(const float4*)&As[buf][k][ty * 8];
            *(float4*)(a + 4) = *(const float4*)&As[buf][k][ty * 8 + 4];
            *(float4*)(b)     = *(const float4*)&Bs[buf][k][tx * 8];
            *(float4*)(b + 4) = *(const float4*)&Bs[buf][k][tx * 8 + 4];
#pragma unroll
            for (int i = 0; i < 8; ++i)
#pragma unroll
                for (int j = 0; j < 8; ++j)
                    acc[i][j] = fmaf(a[i], b[j], acc[i][j]);
        }

        // Store prefetched tile into the other buffer
        int nb = buf ^ 1;
#pragma unroll
        for (int i = 0; i < 2; ++i) {
            int r = aRow + i * 64;
            As[nb][aCol + 0][r] = aReg[i].x;
            As[nb][aCol + 1][r] = aReg[i].y;
            As[nb][aCol + 2][r] = aReg[i].z;
            As[nb][aCol + 3][r] = aReg[i].w;
        }
#pragma unroll
        for (int i = 0; i < 2; ++i) {
            int r = bRow + i * 8;
            *(float4*)&Bs[nb][r][bCol] = bReg[i];
        }
        __syncthreads();
        buf = nb;
    }

    // Final tile
#pragma unroll
    for (int k = 0; k < 16; ++k) {
        float a[8], b[8];
        *(float4*)(a)     = *(const float4*)&As[buf][k][ty * 8];
        *(float4*)(a + 4) = *(const float4*)&As[buf][k][ty * 8 + 4];
        *(float4*)(b)     = *(const float4*)&Bs[buf][k][tx * 8];
        *(float4*)(b + 4) = *(const float4*)&Bs[buf][k][tx * 8 + 4];
#pragma unroll
        for (int i = 0; i < 8; ++i)
#pragma unroll
            for (int j = 0; j < 8; ++j)
                acc[i][j] = fmaf(a[i], b[j], acc[i][j]);
    }

    // store
#pragma unroll
    for (int i = 0; i < 8; ++i) {
        int row = rowBase + ty * 8 + i;
        float* cp = C + (size_t)row * ldc + colC + tx * 8;
        float4 v0 = make_float4(acc[i][0], acc[i][1], acc[i][2], acc[i][3]);
        float4 v1 = make_float4(acc[i][4], acc[i][5], acc[i][6], acc[i][7]);
        *(float4*)(cp)     = v0;
        *(float4*)(cp + 4) = v1;
    }
}

// GEMM 1: fused QKV projection. grid (32, 64), 256 threads.
__global__ __launch_bounds__(256) void gemm_qkv_kernel(
    const float* __restrict__ h,
    const float* __restrict__ wq,
    const float* __restrict__ wk,
    const float* __restrict__ wv)
{
    int colC = blockIdx.x * 128;
    const float* W;
    int ldw, colW;
    if (colC < 2048)       { W = wq; ldw = 2048; colW = colC; }
    else if (colC < 3072)  { W = wk; ldw = 1024; colW = colC - 2048; }
    else                   { W = wv; ldw = 1024; colW = colC - 3072; }
    sgemm_body(h, EE, W, ldw, g_qkv, NQKV, EE, blockIdx.y * 128, colW, colC);
}

// GEMM 2: output projection into d_out. grid (8, 64), 256 threads.
__global__ __launch_bounds__(256) void gemm_out_kernel(
    const float* __restrict__ wo, float* __restrict__ out)
{
    sgemm_body(g_x, HH * DD, wo, EE, out, EE, HH * DD,
               blockIdx.y * 128, blockIdx.x * 128, blockIdx.x * 128);
}

// ---------------------------------------------------------------------------
// RMSNorm + partial RoPE + transpose. One warp per (m, h).
// ---------------------------------------------------------------------------
__global__ __launch_bounds__(256) void norm_rope_kernel(
    const float* __restrict__ cosb,
    const float* __restrict__ sinb,
    const float* __restrict__ qw,
    const float* __restrict__ kw)
{
    const int tid = threadIdx.x;
    const int lane = tid & 31;
    const int w = blockIdx.x * 8 + (tid >> 5);
    const int m = w >> 4;          // 0..8191
    const int h = w & 15;
    const int b = m >> 11;
    const int l = m & 2047;

    const float* row = g_qkv + (size_t)m * NQKV;
    const int d0 = lane, d1 = lane + 32;

    float q0 = row[h * 128 + d0],       q1 = row[h * 128 + d1];
    float g0 = row[h * 128 + 64 + d0],  g1 = row[h * 128 + 64 + d1];
    float k0 = row[2048 + h * 64 + d0], k1 = row[2048 + h * 64 + d1];
    float v0 = row[3072 + h * 64 + d0], v1 = row[3072 + h * 64 + d1];

    float ssq = q0 * q0 + q1 * q1;
    float ssk = k0 * k0 + k1 * k1;
#pragma unroll
    for (int off = 16; off > 0; off >>= 1) {
        ssq += __shfl_xor_sync(0xffffffffu, ssq, off);
        ssk += __shfl_xor_sync(0xffffffffu, ssk, off);
    }
    float rq = rsqrtf(ssq * (1.0f / 64.0f) + 1e-6f);
    float rk = rsqrtf(ssk * (1.0f / 64.0f) + 1e-6f);

    float qn0 = q0 * rq * qw[d0], qn1 = q1 * rq * qw[d1];
    float kn0 = k0 * rk * kw[d0], kn1 = k1 * rk * kw[d1];

    const bool rot = lane < 24;   // band % 32 < 24 (same for d0 and d1)
    size_t cb = ((size_t)b * LL + l) * DD;
    float c0 = cosb[cb + d0], c1 = cosb[cb + d1];
    float s0 = sinb[cb + d0], s1 = sinb[cb + d1];

    float qr0 = rot ? (qn0 * c0 - qn1 * s0) : qn0;
    float qr1 = rot ? (qn1 * c1 + qn0 * s1) : qn1;
    float kr0 = rot ? (kn0 * c0 - kn1 * s0) : kn0;
    float kr1 = rot ? (kn1 * c1 + kn0 * s1) : kn1;

    size_t ob = ((size_t)(b * HH + h) * LL + l) * DD;
    g_q[ob + d0] = qr0; g_q[ob + d1] = qr1;
    g_k[ob + d0] = kr0; g_k[ob + d1] = kr1;
    g_v[ob + d0] = v0;  g_v[ob + d1] = v1;

    size_t gb = (size_t)m * (HH * DD) + h * DD;
    g_gate[gb + d0] = g0; g_gate[gb + d1] = g1;
}

// ---------------------------------------------------------------------------
// Flash attention: 64 query rows x full K sweep per block.
// grid (L/64=32, B*H=64), 256 threads, (tx,ty) 16x16, 4x4 per-thread tile.
// Mask tile prefetched into registers at top of each iteration so its DRAM
// latency is hidden behind the smem barriers + K/V loads + S-GEMM.
// Fuses sigmoid gating into epilogue; writes [B,L,H*D] into g_x.
// ---------------------------------------------------------------------------
#define FL_SMEM (4 * 64 * 68 * 4)

__global__ __launch_bounds__(256) void flash_kernel(
    const float* __restrict__ mask)
{
    extern __shared__ float sm[];
    float* Qs = sm;                 // [k][row], stride 68 (k-major)
    float* Ks = sm + 64 * 68;       // [k][col]
    float* Vs = sm + 2 * 64 * 68;   // [key][d]
    float* Ps = sm + 3 * 64 * 68;   // [key][row]

    const int tid = threadIdx.x;
    const int tx = tid & 15, ty = tid >> 4;
    const int r0 = ty * 4, c0 = tx * 4;

    const int qt = blockIdx.x, bh = blockIdx.y;
    const int b = bh >> 4, hh = bh & 15;
    const int q0 = qt * 64;
    const float scale = 0.125f;     // 1/sqrt(64)

    // Load Q tile (pre-scaled), transposed into smem.
    const float* Qg = g_q + ((size_t)bh * LL + q0) * DD;
#pragma unroll
    for (int i = 0; i < 4; ++i) {
        int f = i * 256 + tid;
        int row = f >> 4;
        int c4 = (f & 15) << 2;
        float4 v = *(const float4*)(Qg + row * DD + c4);
        Qs[(c4 + 0) * 68 + row] = v.x * scale;
        Qs[(c4 + 1) * 68 + row] = v.y * scale;
        Qs[(c4 + 2) * 68 + row] = v.z * scale;
        Qs[(c4 + 3) * 68 + row] = v.w * scale;
    }

    float O[4][4];
#pragma unroll
    for (int i = 0; i < 4; ++i)
#pragma unroll
        for (int j = 0; j < 4; ++j) O[i][j] = 0.f;
    float m_i[4] = {-1e30f, -1e30f, -1e30f, -1e30f};
    float l_i[4] = {0.f, 0.f, 0.f, 0.f};

    const float* Kg = g_k + (size_t)bh * LL * DD;
    const float* Vg = g_v + (size_t)bh * LL * DD;
    const float* Mg = mask + (size_t)b * LL * LL + (size_t)q0 * LL;

    for (int k0 = 0; k0 < LL; k0 += 64) {
        // Prefetch mask tile into registers FIRST (pure GMEM, no smem deps).
        // Latency hides behind both barriers, the K/V loads, and the S-GEMM.
        float4 mreg[4];
#pragma unroll
        for (int i = 0; i < 4; ++i)
            mreg[i] = *(const float4*)(Mg + (size_t)(r0 + i) * LL + k0 + c0);

        __syncthreads();
        // Load K (transposed) and V tiles
#pragma unroll
        for (int i = 0; i < 4; ++i) {
            int f = i * 256 + tid;
            int row = f >> 4;
            int c4 = (f & 15) << 2;
            float4 kv = *(const float4*)(Kg + (size_t)(k0 + row) * DD + c4);
            Ks[(c4 + 0) * 68 + row] = kv.x;
            Ks[(c4 + 1) * 68 + row] = kv.y;
            Ks[(c4 + 2) * 68 + row] = kv.z;
            Ks[(c4 + 3) * 68 + row] = kv.w;
            float4 vv = *(const float4*)(Vg + (size_t)(k0 + row) * DD + c4);
            *(float4*)&Vs[row * 68 + c4] = vv;
        }
        __syncthreads();

        // S = Q K^T (Q pre-scaled)
        float s[4][4];
#pragma unroll
        for (int i = 0; i < 4; ++i)
#pragma unroll
            for (int j = 0; j < 4; ++j) s[i][j] = 0.f;

#pragma unroll 16
        for (int k = 0; k < 64; ++k) {
            float4 qa = *(const float4*)&Qs[k * 68 + r0];
            float4 kb = *(const float4*)&Ks[k * 68 + c0];
            float av[4] = {qa.x, qa.y, qa.z, qa.w};
            float bv[4] = {kb.x, kb.y, kb.z, kb.w};
#pragma unroll
            for (int i = 0; i < 4; ++i)
#pragma unroll
                for (int j = 0; j < 4; ++j)
                    s[i][j] = fmaf(av[i], bv[j], s[i][j]);
        }

        // + mask (already resident in registers)
#pragma unroll
        for (int i = 0; i < 4; ++i) {
            s[i][0] += mreg[i].x; s[i][1] += mreg[i].y;
            s[i][2] += mreg[i].z; s[i][3] += mreg[i].w;
        }

        // Online softmax (row groups = 16 lanes sharing ty, within one warp)
#pragma unroll
        for (int i = 0; i < 4; ++i) {
            float mloc = fmaxf(fmaxf(s[i][0], s[i][1]), fmaxf(s[i][2], s[i][3]));
#pragma unroll
            for (int off = 1; off < 16; off <<= 1)
                mloc = fmaxf(mloc, __shfl_xor_sync(0xffffffffu, mloc, off));
            float mnew = fmaxf(m_i[i], mloc);
            float corr = __expf(m_i[i] - mnew);
            float p[4];
            float rs = 0.f;
#pragma unroll
            for (int j = 0; j < 4; ++j) {
                p[j] = __expf(s[i][j] - mnew);
                rs += p[j];
            }
#pragma unroll
            for (int off = 1; off < 16; off <<= 1)
                rs += __shfl_xor_sync(0xffffffffu, rs, off);
            l_i[i] = l_i[i] * corr + rs;
            m_i[i] = mnew;
#pragma unroll
            for (int jj = 0; jj < 4; ++jj) O[i][jj] *= corr;
            // store P transposed: Ps[key][row]
#pragma unroll
            for (int j = 0; j < 4; ++j)
                Ps[(c0 + j) * 68 + r0 + i] = p[j];
        }
        __syncwarp();

        // O += P V
#pragma unroll 8
        for (int j = 0; j < 64; ++j) {
            float4 pa = *(const float4*)&Ps[j * 68 + r0];
            float4 vv = *(const float4*)&Vs[j * 68 + c0];
            float pav[4] = {pa.x, pa.y, pa.z, pa.w};
            float vvv[4] = {vv.x, vv.y, vv.z, vv.w};
#pragma unroll
            for (int i = 0; i < 4; ++i)
#pragma unroll
                for (int jj = 0; jj < 4; ++jj)
                    O[i][jj] = fmaf(pav[i], vvv[jj], O[i][jj]);
        }
    }

    // Epilogue: normalize, sigmoid gate, write [B, L, H*D]
#pragma unroll
    for (int i = 0; i < 4; ++i) {
        float inv = 1.0f / l_i[i];
        int lq = q0 + r0 + i;
        size_t base = ((size_t)b * LL + lq) * (HH * DD) + hh * DD + c0;
        float4 gv = *(const float4*)&g_gate[base];
        float4 ov;
        ov.x = O[i][0] * inv * (1.0f / (1.0f + __expf(-gv.x)));
        ov.y = O[i][1] * inv * (1.0f / (1.0f + __expf(-gv.y)));
        ov.z = O[i][2] * inv * (1.0f / (1.0f + __expf(-gv.z)));
        ov.w = O[i][3] * inv * (1.0f / (1.0f + __expf(-gv.w)));
        *(float4*)&g_x[base] = ov;
    }
}

// ---------------------------------------------------------------------------
extern "C" void kernel_launch(void* const* d_in, const int* in_sizes, int n_in,
                              void* d_out, int out_size)
{
    const float* h    = (const float*)d_in[0];
    const float* cosb = (const float*)d_in[1];
    const float* sinb = (const float*)d_in[2];
    const float* mask = (const float*)d_in[3];
    const float* wq   = (const float*)d_in[4];
    const float* wk   = (const float*)d_in[5];
    const float* wv   = (const float*)d_in[6];
    const float* wo   = (const float*)d_in[7];
    const float* qw   = (const float*)d_in[8];
    const float* kw   = (const float*)d_in[9];
    float* out = (float*)d_out;

    cudaFuncSetAttribute(flash_kernel,
                         cudaFuncAttributeMaxDynamicSharedMemorySize, FL_SMEM);

    gemm_qkv_kernel<<<dim3(NQKV / 128, MM / 128), 256>>>(h, wq, wk, wv);
    norm_rope_kernel<<<(MM * HH) / 8, 256>>>(cosb, sinb, qw, kw);
    flash_kernel<<<dim3(LL / 64, BB * HH), 256, FL_SMEM>>>(mask);
    gemm_out_kernel<<<dim3(EE / 128, MM / 128), 256>>>(wo, out);
}

// round 14
// speedup vs baseline: 1.3776x; 1.3776x over previous
#include <cuda_runtime.h>
#include <cuda_bf16.h>
#include <cstdint>

// Problem constants
#define BB 4
#define LL 2048
#define EE 1024
#define HH 16
#define DD 64
#define MM (BB * LL)          // 8192
#define NQKV 4096             // 2048 (q+gate) + 1024 (k) + 1024 (v)

// Scratch (device globals; no allocation allowed)
__device__ float g_qkv[(size_t)MM * NQKV];
__device__ float g_q[(size_t)BB * HH * LL * DD];
__device__ float g_k[(size_t)BB * HH * LL * DD];
__device__ float g_v[(size_t)BB * HH * LL * DD];
__device__ float g_gate[(size_t)MM * HH * DD];
__device__ float g_x[(size_t)MM * HH * DD];

// bf16 hi/lo splits for tensor-core GEMMs
__device__ __nv_bfloat16 g_a_hi[(size_t)MM * EE];      // h split
__device__ __nv_bfloat16 g_a_lo[(size_t)MM * EE];
__device__ __nv_bfloat16 g_wt_hi[(size_t)NQKV * EE];   // [wq|wk|wv]^T split
__device__ __nv_bfloat16 g_wt_lo[(size_t)NQKV * EE];
__device__ __nv_bfloat16 g_wot_hi[(size_t)EE * EE];    // wo^T split
__device__ __nv_bfloat16 g_wot_lo[(size_t)EE * EE];
__device__ __nv_bfloat16 g_x_hi[(size_t)MM * EE];      // g_x split
__device__ __nv_bfloat16 g_x_lo[(size_t)MM * EE];

// ---------------------------------------------------------------------------
// PTX helpers — all legal on plain compute_103 (sm_80-era features)
// ---------------------------------------------------------------------------
static __device__ __forceinline__ uint32_t smem_u32(const void* p) {
    uint32_t a;
    asm("{ .reg .u64 t; cvta.to.shared.u64 t, %1; cvt.u32.u64 %0, t; }"
        : "=r"(a) : "l"(p));
    return a;
}

#define CP_ASYNC16(saddr, gptr) \
    asm volatile("cp.async.cg.shared.global [%0], [%1], 16;" \
                 :: "r"(saddr), "l"(gptr))
#define CP_COMMIT() asm volatile("cp.async.commit_group;" ::: "memory")
#define CP_WAIT0()  asm volatile("cp.async.wait_group 0;" ::: "memory")

#define LDSM_X4(r0, r1, r2, r3, addr) \
    asm volatile("ldmatrix.sync.aligned.m8n8.x4.shared.b16 {%0,%1,%2,%3}, [%4];" \
                 : "=r"(r0), "=r"(r1), "=r"(r2), "=r"(r3) : "r"(addr))
#define LDSM_X2(r0, r1, addr) \
    asm volatile("ldmatrix.sync.aligned.m8n8.x2.shared.b16 {%0,%1}, [%2];" \
                 : "=r"(r0), "=r"(r1) : "r"(addr))

static __device__ __forceinline__ void mma_bf16(
    float* d, const uint32_t* a, const uint32_t* b)
{
    asm volatile(
        "mma.sync.aligned.m16n8k16.row.col.f32.bf16.bf16.f32 "
        "{%0,%1,%2,%3}, {%4,%5,%6,%7}, {%8,%9}, {%0,%1,%2,%3};"
        : "+f"(d[0]), "+f"(d[1]), "+f"(d[2]), "+f"(d[3])
        : "r"(a[0]), "r"(a[1]), "r"(a[2]), "r"(a[3]), "r"(b[0]), "r"(b[1]));
}

// ---------------------------------------------------------------------------
// Split fp32 -> bf16 hi/lo (same layout).
// ---------------------------------------------------------------------------
__global__ __launch_bounds__(256) void split_kernel(
    const float* __restrict__ src,
    __nv_bfloat16* __restrict__ hi, __nv_bfloat16* __restrict__ lo)
{
    size_t i = ((size_t)blockIdx.x * 256 + threadIdx.x) * 4;
    float4 v = *(const float4*)(src + i);
    float f[4] = {v.x, v.y, v.z, v.w};
    __nv_bfloat16 h[4], l[4];
#pragma unroll
    for (int j = 0; j < 4; ++j) {
        h[j] = __float2bfloat16(f[j]);
        l[j] = __float2bfloat16(f[j] - __bfloat162float(h[j]));
    }
    *(uint2*)(hi + i) = *(uint2*)h;
    *(uint2*)(lo + i) = *(uint2*)l;
}

// ---------------------------------------------------------------------------
// Transpose + split: dst[n][k] = W[k][n], K=1024 rows.
// ---------------------------------------------------------------------------
__global__ __launch_bounds__(256) void tr_split_kernel(
    const float* __restrict__ W, int ldw,
    __nv_bfloat16* __restrict__ dhi, __nv_bfloat16* __restrict__ dlo)
{
    __shared__ float t[32][33];
    int n0 = blockIdx.x * 32, k0 = blockIdx.y * 32;
#pragma unroll
    for (int r = threadIdx.y; r < 32; r += 8)
        t[threadIdx.x][r] = W[(size_t)(k0 + r) * ldw + n0 + threadIdx.x];
    __syncthreads();
#pragma unroll
    for (int r = threadIdx.y; r < 32; r += 8) {
        float v = t[r][threadIdx.x];
        __nv_bfloat16 h = __float2bfloat16(v);
        __nv_bfloat16 l = __float2bfloat16(v - __bfloat162float(h));
        size_t o = (size_t)(n0 + r) * EE + k0 + threadIdx.x;
        dhi[o] = h; dlo[o] = l;
    }
}

// ---------------------------------------------------------------------------
// Tensor-core GEMM via mma.sync bf16 (3-term hi/lo emulated fp32).
// C[128,128] per CTA, K=1024 in 16 chunks of 64, cp.async double buffer.
// 8 warps in 2(M)x4(N): warp tile 64x32 = 4x4 m16n8k16.
// A: [M,1024] bf16 row-major. B: [N,1024] bf16 row-major (= K x N col-major).
// ---------------------------------------------------------------------------
#define KDIM 1024
#define TSTRIDE 144                 // bytes per smem row (72 bf16, pad 8)
#define TILE_BYTES (128 * TSTRIDE)  // 18432
#define BUF_BYTES (4 * TILE_BYTES)  // 73728: Ahi, Alo, Bhi, Blo
#define MMA_SMEM (2 * BUF_BYTES)    // 147456

static __device__ __forceinline__ void issue_chunk(
    uint32_t sbase, int buf, int tid, int rowBase, int colBase, int k0,
    const __nv_bfloat16* Ahi, const __nv_bfloat16* Alo,
    const __nv_bfloat16* Bhi, const __nv_bfloat16* Blo)
{
#pragma unroll
    for (int i = 0; i < 4; ++i) {
        int idx = i * 256 + tid;
        int r = idx >> 3;            // 0..127
        int u4 = idx & 7;            // 16B unit within 128B row
        uint32_t so = (uint32_t)buf * BUF_BYTES + (uint32_t)r * TSTRIDE + u4 * 16;
        int ke = k0 + u4 * 8;
        CP_ASYNC16(sbase + 0 * TILE_BYTES + so, Ahi + (size_t)(rowBase + r) * KDIM + ke);
        CP_ASYNC16(sbase + 1 * TILE_BYTES + so, Alo + (size_t)(rowBase + r) * KDIM + ke);
        CP_ASYNC16(sbase + 2 * TILE_BYTES + so, Bhi + (size_t)(colBase + r) * KDIM + ke);
        CP_ASYNC16(sbase + 3 * TILE_BYTES + so, Blo + (size_t)(colBase + r) * KDIM + ke);
    }
    CP_COMMIT();
}

__global__ __launch_bounds__(256) void mma_gemm_kernel(
    const __nv_bfloat16* __restrict__ Ahi, const __nv_bfloat16* __restrict__ Alo,
    const __nv_bfloat16* __restrict__ Bhi, const __nv_bfloat16* __restrict__ Blo,
    float* __restrict__ C, int ldc)
{
    extern __shared__ char smem[];
    const uint32_t sbase = smem_u32(smem);
    const int tid = threadIdx.x;
    const int wid = tid >> 5, lane = tid & 31;
    const int warpM = wid >> 2;      // 0..1, 64 rows each
    const int warpN = wid & 3;       // 0..3, 32 cols each
    const int rowBase = blockIdx.y * 128, colBase = blockIdx.x * 128;

    float d[4][4][4];
#pragma unroll
    for (int mt = 0; mt < 4; ++mt)
#pragma unroll
        for (int nt = 0; nt < 4; ++nt)
#pragma unroll
            for (int j = 0; j < 4; ++j) d[mt][nt][j] = 0.f;

    // ldmatrix per-lane address components (canonical m16n8k16 fragments)
    const int aRow = warpM * 64 + (lane & 15);
    const int aKsel = ((lane >> 4) << 3);        // 0 or 8
    const int bRow = warpN * 32 + (lane & 7);
    const int bKsel = (((lane >> 3) & 1) << 3);  // 0 or 8 (lanes 0-15 used)

    issue_chunk(sbase, 0, tid, rowBase, colBase, 0, Ahi, Alo, Bhi, Blo);

    int buf = 0;
    for (int c = 0; c < 16; ++c) {
        CP_WAIT0();
        __syncthreads();
        if (c < 15)
            issue_chunk(sbase, buf ^ 1, tid, rowBase, colBase, (c + 1) * 64,
                        Ahi, Alo, Bhi, Blo);

        const uint32_t base = sbase + (uint32_t)buf * BUF_BYTES;
#pragma unroll
        for (int kk = 0; kk < 64; kk += 16) {
            uint32_t ahi[4][4], alo[4][4], bhi[4][2], blo[4][2];
#pragma unroll
            for (int mt = 0; mt < 4; ++mt) {
                uint32_t ad = base + (uint32_t)(aRow + mt * 16) * TSTRIDE
                            + (uint32_t)(kk + aKsel) * 2;
                LDSM_X4(ahi[mt][0], ahi[mt][1], ahi[mt][2], ahi[mt][3], ad);
                LDSM_X4(alo[mt][0], alo[mt][1], alo[mt][2], alo[mt][3],
                        ad + TILE_BYTES);
            }
#pragma unroll
            for (int nt = 0; nt < 4; ++nt) {
                uint32_t bd = base + 2 * TILE_BYTES
                            + (uint32_t)(bRow + nt * 8) * TSTRIDE
                            + (uint32_t)(kk + bKsel) * 2;
                LDSM_X2(bhi[nt][0], bhi[nt][1], bd);
                LDSM_X2(blo[nt][0], blo[nt][1], bd + TILE_BYTES);
            }
#pragma unroll
            for (int mt = 0; mt < 4; ++mt)
#pragma unroll
                for (int nt = 0; nt < 4; ++nt) {
                    mma_bf16(d[mt][nt], ahi[mt], bhi[nt]);
                    mma_bf16(d[mt][nt], ahi[mt], blo[nt]);
                    mma_bf16(d[mt][nt], alo[mt], bhi[nt]);
                }
        }
        buf ^= 1;
    }

    // Epilogue: c0/c1 -> row lane>>2, c2/c3 -> row+8; cols (lane&3)*2, +1.
    const int cRow = rowBase + warpM * 64 + (lane >> 2);
    const int cCol = colBase + warpN * 32 + (lane & 3) * 2;
#pragma unroll
    for (int mt = 0; mt < 4; ++mt)
#pragma unroll
        for (int nt = 0; nt < 4; ++nt) {
            float2 v0 = make_float2(d[mt][nt][0], d[mt][nt][1]);
            float2 v1 = make_float2(d[mt][nt][2], d[mt][nt][3]);
            *(float2*)&C[(size_t)(cRow + mt * 16) * ldc + cCol + nt * 8] = v0;
            *(float2*)&C[(size_t)(cRow + mt * 16 + 8) * ldc + cCol + nt * 8] = v1;
        }
}

// ---------------------------------------------------------------------------
// RMSNorm + partial RoPE + transpose. One warp per (m, h).  (unchanged)
// ---------------------------------------------------------------------------
__global__ __launch_bounds__(256) void norm_rope_kernel(
    const float* __restrict__ cosb,
    const float* __restrict__ sinb,
    const float* __restrict__ qw,
    const float* __restrict__ kw)
{
    const int tid = threadIdx.x;
    const int lane = tid & 31;
    const int w = blockIdx.x * 8 + (tid >> 5);
    const int m = w >> 4;
    const int h = w & 15;
    const int b = m >> 11;
    const int l = m & 2047;

    const float* row = g_qkv + (size_t)m * NQKV;
    const int d0 = lane, d1 = lane + 32;

    float q0 = row[h * 128 + d0],       q1 = row[h * 128 + d1];
    float g0 = row[h * 128 + 64 + d0],  g1 = row[h * 128 + 64 + d1];
    float k0 = row[2048 + h * 64 + d0], k1 = row[2048 + h * 64 + d1];
    float v0 = row[3072 + h * 64 + d0], v1 = row[3072 + h * 64 + d1];

    float ssq = q0 * q0 + q1 * q1;
    float ssk = k0 * k0 + k1 * k1;
#pragma unroll
    for (int off = 16; off > 0; off >>= 1) {
        ssq += __shfl_xor_sync(0xffffffffu, ssq, off);
        ssk += __shfl_xor_sync(0xffffffffu, ssk, off);
    }
    float rq = rsqrtf(ssq * (1.0f / 64.0f) + 1e-6f);
    float rk = rsqrtf(ssk * (1.0f / 64.0f) + 1e-6f);

    float qn0 = q0 * rq * qw[d0], qn1 = q1 * rq * qw[d1];
    float kn0 = k0 * rk * kw[d0], kn1 = k1 * rk * kw[d1];

    const bool rot = lane < 24;
    size_t cb = ((size_t)b * LL + l) * DD;
    float c0 = cosb[cb + d0], c1 = cosb[cb + d1];
    float s0 = sinb[cb + d0], s1 = sinb[cb + d1];

    float qr0 = rot ? (qn0 * c0 - qn1 * s0) : qn0;
    float qr1 = rot ? (qn1 * c1 + qn0 * s1) : qn1;
    float kr0 = rot ? (kn0 * c0 - kn1 * s0) : kn0;
    float kr1 = rot ? (kn1 * c1 + kn0 * s1) : kn1;

    size_t ob = ((size_t)(b * HH + h) * LL + l) * DD;
    g_q[ob + d0] = qr0; g_q[ob + d1] = qr1;
    g_k[ob + d0] = kr0; g_k[ob + d1] = kr1;
    g_v[ob + d0] = v0;  g_v[ob + d1] = v1;

    size_t gb = (size_t)m * (HH * DD) + h * DD;
    g_gate[gb + d0] = g0; g_gate[gb + d1] = g1;
}

// ---------------------------------------------------------------------------
// Flash attention (unchanged from the passing R8 version).
// ---------------------------------------------------------------------------
#define FL_SMEM (4 * 64 * 68 * 4)

__global__ __launch_bounds__(256) void flash_kernel(
    const float* __restrict__ mask)
{
    extern __shared__ float sm[];
    float* Qs = sm;
    float* Ks = sm + 64 * 68;
    float* Vs = sm + 2 * 64 * 68;
    float* Ps = sm + 3 * 64 * 68;

    const int tid = threadIdx.x;
    const int tx = tid & 15, ty = tid >> 4;
    const int r0 = ty * 4, c0 = tx * 4;

    const int qt = blockIdx.x, bh = blockIdx.y;
    const int b = bh >> 4, hh = bh & 15;
    const int q0 = qt * 64;
    const float scale = 0.125f;

    const float* Qg = g_q + ((size_t)bh * LL + q0) * DD;
#pragma unroll
    for (int i = 0; i < 4; ++i) {
        int f = i * 256 + tid;
        int row = f >> 4;
        int c4 = (f & 15) << 2;
        float4 v = *(const float4*)(Qg + row * DD + c4);
        Qs[(c4 + 0) * 68 + row] = v.x * scale;
        Qs[(c4 + 1) * 68 + row] = v.y * scale;
        Qs[(c4 + 2) * 68 + row] = v.z * scale;
        Qs[(c4 + 3) * 68 + row] = v.w * scale;
    }

    float O[4][4];
#pragma unroll
    for (int i = 0; i < 4; ++i)
#pragma unroll
        for (int j = 0; j < 4; ++j) O[i][j] = 0.f;
    float m_i[4] = {-1e30f, -1e30f, -1e30f, -1e30f};
    float l_i[4] = {0.f, 0.f, 0.f, 0.f};

    const float* Kg = g_k + (size_t)bh * LL * DD;
    const float* Vg = g_v + (size_t)bh * LL * DD;
    const float* Mg = mask + (size_t)b * LL * LL + (size_t)q0 * LL;

    for (int k0 = 0; k0 < LL; k0 += 64) {
        float4 mreg[4];
#pragma unroll
        for (int i = 0; i < 4; ++i)
            mreg[i] = *(const float4*)(Mg + (size_t)(r0 + i) * LL + k0 + c0);

        __syncthreads();
#pragma unroll
        for (int i = 0; i < 4; ++i) {
            int f = i * 256 + tid;
            int row = f >> 4;
            int c4 = (f & 15) << 2;
            float4 kv = *(const float4*)(Kg + (size_t)(k0 + row) * DD + c4);
            Ks[(c4 + 0) * 68 + row] = kv.x;
            Ks[(c4 + 1) * 68 + row] = kv.y;
            Ks[(c4 + 2) * 68 + row] = kv.z;
            Ks[(c4 + 3) * 68 + row] = kv.w;
            float4 vv = *(const float4*)(Vg + (size_t)(k0 + row) * DD + c4);
            *(float4*)&Vs[row * 68 + c4] = vv;
        }
        __syncthreads();

        float s[4][4];
#pragma unroll
        for (int i = 0; i < 4; ++i)
#pragma unroll
            for (int j = 0; j < 4; ++j) s[i][j] = 0.f;

#pragma unroll 16
        for (int k = 0; k < 64; ++k) {
            float4 qa = *(const float4*)&Qs[k * 68 + r0];
            float4 kb = *(const float4*)&Ks[k * 68 + c0];
            float av[4] = {qa.x, qa.y, qa.z, qa.w};
            float bv[4] = {kb.x, kb.y, kb.z, kb.w};
#pragma unroll
            for (int i = 0; i < 4; ++i)
#pragma unroll
                for (int j = 0; j < 4; ++j)
                    s[i][j] = fmaf(av[i], bv[j], s[i][j]);
        }

#pragma unroll
        for (int i = 0; i < 4; ++i) {
            s[i][0] += mreg[i].x; s[i][1] += mreg[i].y;
            s[i][2] += mreg[i].z; s[i][3] += mreg[i].w;
        }

#pragma unroll
        for (int i = 0; i < 4; ++i) {
            float mloc = fmaxf(fmaxf(s[i][0], s[i][1]), fmaxf(s[i][2], s[i][3]));
#pragma unroll
            for (int off = 1; off < 16; off <<= 1)
                mloc = fmaxf(mloc, __shfl_xor_sync(0xffffffffu, mloc, off));
            float mnew = fmaxf(m_i[i], mloc);
            float corr = __expf(m_i[i] - mnew);
            float p[4];
            float rs = 0.f;
#pragma unroll
            for (int j = 0; j < 4; ++j) {
                p[j] = __expf(s[i][j] - mnew);
                rs += p[j];
            }
#pragma unroll
            for (int off = 1; off < 16; off <<= 1)
                rs += __shfl_xor_sync(0xffffffffu, rs, off);
            l_i[i] = l_i[i] * corr + rs;
            m_i[i] = mnew;
#pragma unroll
            for (int jj = 0; jj < 4; ++jj) O[i][jj] *= corr;
#pragma unroll
            for (int j = 0; j < 4; ++j)
                Ps[(c0 + j) * 68 + r0 + i] = p[j];
        }
        __syncwarp();

#pragma unroll 8
        for (int j = 0; j < 64; ++j) {
            float4 pa = *(const float4*)&Ps[j * 68 + r0];
            float4 vv = *(const float4*)&Vs[j * 68 + c0];
            float pav[4] = {pa.x, pa.y, pa.z, pa.w};
            float vvv[4] = {vv.x, vv.y, vv.z, vv.w};
#pragma unroll
            for (int i = 0; i < 4; ++i)
#pragma unroll
                for (int jj = 0; jj < 4; ++jj)
                    O[i][jj] = fmaf(pav[i], vvv[jj], O[i][jj]);
        }
    }

#pragma unroll
    for (int i = 0; i < 4; ++i) {
        float inv = 1.0f / l_i[i];
        int lq = q0 + r0 + i;
        size_t base = ((size_t)b * LL + lq) * (HH * DD) + hh * DD + c0;
        float4 gv = *(const float4*)&g_gate[base];
        float4 ov;
        ov.x = O[i][0] * inv * (1.0f / (1.0f + __expf(-gv.x)));
        ov.y = O[i][1] * inv * (1.0f / (1.0f + __expf(-gv.y)));
        ov.z = O[i][2] * inv * (1.0f / (1.0f + __expf(-gv.z)));
        ov.w = O[i][3] * inv * (1.0f / (1.0f + __expf(-gv.w)));
        *(float4*)&g_x[base] = ov;
    }
}

// ---------------------------------------------------------------------------
extern "C" void kernel_launch(void* const* d_in, const int* in_sizes, int n_in,
                              void* d_out, int out_size)
{
    const float* h    = (const float*)d_in[0];
    const float* cosb = (const float*)d_in[1];
    const float* sinb = (const float*)d_in[2];
    const float* mask = (const float*)d_in[3];
    const float* wq   = (const float*)d_in[4];
    const float* wk   = (const float*)d_in[5];
    const float* wv   = (const float*)d_in[6];
    const float* wo   = (const float*)d_in[7];
    const float* qw   = (const float*)d_in[8];
    const float* kw   = (const float*)d_in[9];
    float* out = (float*)d_out;

    cudaFuncSetAttribute(flash_kernel,
                         cudaFuncAttributeMaxDynamicSharedMemorySize, FL_SMEM);
    cudaFuncSetAttribute(mma_gemm_kernel,
                         cudaFuncAttributeMaxDynamicSharedMemorySize, MMA_SMEM);

    // Resolve device-global scratch addresses (host side).
    __nv_bfloat16 *a_hi, *a_lo, *wt_hi, *wt_lo, *wot_hi, *wot_lo, *x_hi, *x_lo;
    float *qkvp, *xp;
    cudaGetSymbolAddress((void**)&a_hi,  g_a_hi);
    cudaGetSymbolAddress((void**)&a_lo,  g_a_lo);
    cudaGetSymbolAddress((void**)&wt_hi, g_wt_hi);
    cudaGetSymbolAddress((void**)&wt_lo, g_wt_lo);
    cudaGetSymbolAddress((void**)&wot_hi, g_wot_hi);
    cudaGetSymbolAddress((void**)&wot_lo, g_wot_lo);
    cudaGetSymbolAddress((void**)&x_hi,  g_x_hi);
    cudaGetSymbolAddress((void**)&x_lo,  g_x_lo);
    cudaGetSymbolAddress((void**)&qkvp,  g_qkv);
    cudaGetSymbolAddress((void**)&xp,    g_x);

    // 1. Split h; transpose+split weights.
    split_kernel<<<(MM * EE) / 1024, 256>>>(h, a_hi, a_lo);
    tr_split_kernel<<<dim3(2048 / 32, EE / 32), dim3(32, 8)>>>(wq, 2048, wt_hi, wt_lo);
    tr_split_kernel<<<dim3(1024 / 32, EE / 32), dim3(32, 8)>>>(
        wk, 1024, wt_hi + (size_t)2048 * EE, wt_lo + (size_t)2048 * EE);
    tr_split_kernel<<<dim3(1024 / 32, EE / 32), dim3(32, 8)>>>(
        wv, 1024, wt_hi + (size_t)3072 * EE, wt_lo + (size_t)3072 * EE);
    tr_split_kernel<<<dim3(1024 / 32, EE / 32), dim3(32, 8)>>>(wo, 1024, wot_hi, wot_lo);

    // 2. QKV projection on tensor cores.
    mma_gemm_kernel<<<dim3(NQKV / 128, MM / 128), 256, MMA_SMEM>>>(
        a_hi, a_lo, wt_hi, wt_lo, qkvp, NQKV);

    // 3. Norm + RoPE + transpose.
    norm_rope_kernel<<<(MM * HH) / 8, 256>>>(cosb, sinb, qw, kw);

    // 4. Flash attention + gating.
    flash_kernel<<<dim3(LL / 64, BB * HH), 256, FL_SMEM>>>(mask);

    // 5. Split gated output; output projection on tensor cores.
    split_kernel<<<(MM * EE) / 1024, 256>>>(xp, x_hi, x_lo);
    mma_gemm_kernel<<<dim3(EE / 128, MM / 128), 256, MMA_SMEM>>>(
        x_hi, x_lo, wot_hi, wot_lo, out, EE);
}